// round 8
// baseline (speedup 1.0000x reference)
#include <cuda_runtime.h>
#include <cuda_bf16.h>
#include <math_constants.h>

// Problem constants
#define N_NODES 50000
#define E_EDGES 800000
#define IN_F    256
#define OUT_F   128
#define NEG_SLOPE 0.2f
#define ALPHA   0.5f

// -------- scratch (static device globals; no allocation allowed) --------
__device__ float g_ft[(size_t)N_NODES * OUT_F];   // projected features [N,128]
__device__ float g_el[N_NODES];
__device__ float g_er[N_NODES];
__device__ float g_sumE[N_NODES];   // sum -> reciprocal after scan kernel
__device__ float g_sumW[N_NODES];
__device__ float g_zE[E_EDGES];
__device__ float g_zW[E_EDGES];
__device__ int   g_deg[N_NODES];       // per-dst degree
__device__ int   g_rowstart[N_NODES + 1];
__device__ int   g_pos[N_NODES];       // working cursor for scatter
__device__ float g_a[E_EDGES];         // blended coefficient, CSR-permuted
__device__ int   g_srcp[E_EDGES];      // src node id, CSR-permuted

// -------- K0: zero softmax sums + degree counters --------
__global__ void k_init() {
    int i = blockIdx.x * blockDim.x + threadIdx.x;
    if (i < N_NODES) {
        g_sumE[i] = 0.0f;
        g_sumW[i] = 0.0f;
        g_deg[i]  = 0;
    }
}

// -------- K1: SGEMM ft = feat(50000x256) @ fc_w(256x128), fused el/er dots --------
// BM=64, BN=128, BK=16, 256 threads, 4x8 register tile per thread.
#define BM 64
#define BN 128
#define BK 16
__global__ __launch_bounds__(256) void k_gemm(const float* __restrict__ A,
                                              const float* __restrict__ B,
                                              const float* __restrict__ attn_l,
                                              const float* __restrict__ attn_r) {
    __shared__ float As[BK][BM + 4];
    __shared__ float Bs[BK][BN];

    const int tid = threadIdx.x;
    const int tx = tid & 15;      // 0..15 -> col group (8 cols each)
    const int ty = tid >> 4;      // 0..15 -> row group (4 rows each)
    const int blockRow = blockIdx.x * BM;

    const int aRow  = tid >> 2;          // 0..63
    const int aCol4 = (tid & 3) << 2;    // 0,4,8,12
    const int bRow  = tid >> 5;          // 0..7
    const int bCol4 = (tid & 31) << 2;   // 0..124

    float acc[4][8];
#pragma unroll
    for (int r = 0; r < 4; r++)
#pragma unroll
        for (int c = 0; c < 8; c++) acc[r][c] = 0.0f;

    const int gRowA = blockRow + aRow;
    const bool aValid = (gRowA < N_NODES);
    const float* Aptr = A + (size_t)gRowA * IN_F + aCol4;

    for (int k0 = 0; k0 < IN_F; k0 += BK) {
        float4 av = aValid ? *(const float4*)(Aptr + k0)
                           : make_float4(0.f, 0.f, 0.f, 0.f);
        As[aCol4 + 0][aRow] = av.x;
        As[aCol4 + 1][aRow] = av.y;
        As[aCol4 + 2][aRow] = av.z;
        As[aCol4 + 3][aRow] = av.w;

        float4 bv0 = *(const float4*)&B[(size_t)(k0 + bRow) * OUT_F + bCol4];
        float4 bv1 = *(const float4*)&B[(size_t)(k0 + bRow + 8) * OUT_F + bCol4];
        *(float4*)&Bs[bRow][bCol4]     = bv0;
        *(float4*)&Bs[bRow + 8][bCol4] = bv1;

        __syncthreads();

#pragma unroll
        for (int k = 0; k < BK; k++) {
            float ar[4], br[8];
#pragma unroll
            for (int r = 0; r < 4; r++) ar[r] = As[k][ty * 4 + r];
#pragma unroll
            for (int c = 0; c < 8; c++) br[c] = Bs[k][tx * 8 + c];
#pragma unroll
            for (int r = 0; r < 4; r++)
#pragma unroll
                for (int c = 0; c < 8; c++) acc[r][c] = fmaf(ar[r], br[c], acc[r][c]);
        }
        __syncthreads();
    }

    float al[8], arr[8];
#pragma unroll
    for (int c = 0; c < 8; c++) {
        al[c]  = attn_l[tx * 8 + c];
        arr[c] = attn_r[tx * 8 + c];
    }

#pragma unroll
    for (int r = 0; r < 4; r++) {
        int gRow = blockRow + ty * 4 + r;
        bool valid = (gRow < N_NODES);
        if (valid) {
            float* o = &g_ft[(size_t)gRow * OUT_F + tx * 8];
            *(float4*)(o + 0) = make_float4(acc[r][0], acc[r][1], acc[r][2], acc[r][3]);
            *(float4*)(o + 4) = make_float4(acc[r][4], acc[r][5], acc[r][6], acc[r][7]);
        }
        float pl = 0.0f, pr = 0.0f;
#pragma unroll
        for (int c = 0; c < 8; c++) {
            pl = fmaf(acc[r][c], al[c],  pl);
            pr = fmaf(acc[r][c], arr[c], pr);
        }
#pragma unroll
        for (int off = 8; off > 0; off >>= 1) {
            pl += __shfl_down_sync(0xFFFFFFFFu, pl, off, 16);
            pr += __shfl_down_sync(0xFFFFFFFFu, pr, off, 16);
        }
        if (tx == 0 && valid) {
            g_el[gRow] = pl;
            g_er[gRow] = pr;
        }
    }
}

// -------- K2: edge pass: score + exp + segment sums + degree histogram --------
// (no max pass: softmax is shift-invariant; scores are O(10), exp can't overflow)
__global__ void k_edge(const float* __restrict__ w,
                       const int* __restrict__ src,
                       const int* __restrict__ dst) {
    int e = blockIdx.x * blockDim.x + threadIdx.x;
    if (e >= E_EDGES) return;
    int s = __ldg(&src[e]), d = __ldg(&dst[e]);
    float sc = g_el[s] + g_er[d];
    sc = (sc > 0.0f) ? sc : NEG_SLOPE * sc;
    float zE = __expf(sc);
    float zW = __expf(__ldg(&w[e]));
    g_zE[e] = zE;
    g_zW[e] = zW;
    atomicAdd(&g_sumE[d], zE);
    atomicAdd(&g_sumW[d], zW);
    atomicAdd(&g_deg[d], 1);
}

// -------- K3: single-block exclusive scan over degrees + reciprocal of sums --------
#define SCAN_THREADS 1024
#define SCAN_ITEMS   49   // 1024*49 = 50176 >= 50000
__global__ __launch_bounds__(SCAN_THREADS) void k_scan() {
    __shared__ int warp_sums[32];
    int t = threadIdx.x;
    int lane = t & 31, wid = t >> 5;
    int base = t * SCAN_ITEMS;

    // local sum
    int sum = 0;
#pragma unroll 4
    for (int i = 0; i < SCAN_ITEMS; i++) {
        int idx = base + i;
        if (idx < N_NODES) sum += g_deg[idx];
    }
    // warp inclusive scan
    int v = sum;
#pragma unroll
    for (int off = 1; off < 32; off <<= 1) {
        int n = __shfl_up_sync(0xFFFFFFFFu, v, off);
        if (lane >= off) v += n;
    }
    if (lane == 31) warp_sums[wid] = v;
    __syncthreads();
    if (wid == 0) {
        int s = warp_sums[lane];
#pragma unroll
        for (int off = 1; off < 32; off <<= 1) {
            int n = __shfl_up_sync(0xFFFFFFFFu, s, off);
            if (lane >= off) s += n;
        }
        warp_sums[lane] = s;
    }
    __syncthreads();
    int warp_prefix = (wid > 0) ? warp_sums[wid - 1] : 0;
    int run = warp_prefix + (v - sum);   // exclusive prefix for this thread

    for (int i = 0; i < SCAN_ITEMS; i++) {
        int idx = base + i;
        if (idx < N_NODES) {
            g_rowstart[idx] = run;
            g_pos[idx] = run;
            run += g_deg[idx];
            // fold reciprocal pass in here
            float sE = g_sumE[idx], sW = g_sumW[idx];
            g_sumE[idx] = (sE > 0.0f) ? 1.0f / sE : 0.0f;
            g_sumW[idx] = (sW > 0.0f) ? 1.0f / sW : 0.0f;
        }
    }
    if (t == SCAN_THREADS - 1) g_rowstart[N_NODES] = run;
}

// -------- K4: scatter edges into CSR order, with final blended coefficient --------
__global__ void k_scatter(const int* __restrict__ src,
                          const int* __restrict__ dst) {
    int e = blockIdx.x * blockDim.x + threadIdx.x;
    if (e >= E_EDGES) return;
    int d = __ldg(&dst[e]);
    float coef = (1.0f - ALPHA) * g_zE[e] * g_sumE[d]
               + ALPHA * g_zW[e] * g_sumW[d];
    int pos = atomicAdd(&g_pos[d], 1);
    g_a[pos]    = coef;
    g_srcp[pos] = __ldg(&src[e]);
}

// -------- K5: aggregation: warp per node, register accumulate, single store --------
__global__ __launch_bounds__(256) void k_aggregate(float* __restrict__ out,
                                                   const float* __restrict__ bias) {
    int node = (blockIdx.x * blockDim.x + threadIdx.x) >> 5;
    int lane = threadIdx.x & 31;
    if (node >= N_NODES) return;

    int start = g_rowstart[node];
    int end   = g_rowstart[node + 1];

    float4 acc = ((const float4*)bias)[lane];

    for (int t = start; t < end; t += 32) {
        int cnt = min(32, end - t);
        float a = 0.0f;
        int   s = 0;
        if (lane < cnt) {
            a = g_a[t + lane];
            s = g_srcp[t + lane];
        }
#pragma unroll 4
        for (int k = 0; k < cnt; k++) {
            float ak = __shfl_sync(0xFFFFFFFFu, a, k);
            int   sk = __shfl_sync(0xFFFFFFFFu, s, k);
            float4 v = ((const float4*)&g_ft[(size_t)sk * OUT_F])[lane];
            acc.x = fmaf(v.x, ak, acc.x);
            acc.y = fmaf(v.y, ak, acc.y);
            acc.z = fmaf(v.z, ak, acc.z);
            acc.w = fmaf(v.w, ak, acc.w);
        }
    }

    ((float4*)&out[(size_t)node * OUT_F])[lane] = acc;
}

// -------- launch --------
extern "C" void kernel_launch(void* const* d_in, const int* in_sizes, int n_in,
                              void* d_out, int out_size) {
    const float* feat   = (const float*)d_in[0];  // [N,256]
    const float* w      = (const float*)d_in[1];  // [E]
    const float* fc_w   = (const float*)d_in[2];  // [256,128]
    const float* attn_l = (const float*)d_in[3];  // [128]
    const float* attn_r = (const float*)d_in[4];  // [128]
    const float* bias   = (const float*)d_in[5];  // [128]
    const int*   src    = (const int*)d_in[6];    // [E]
    const int*   dst    = (const int*)d_in[7];    // [E]
    float* out = (float*)d_out;                   // [N,1,128]

    // K0: zero sums + degrees
    k_init<<<(N_NODES + 255) / 256, 256>>>();
    // K1: GEMM + fused el/er
    {
        int grid = (N_NODES + BM - 1) / BM;
        k_gemm<<<grid, 256>>>(feat, fc_w, attn_l, attn_r);
    }
    // K2: edge score/exp/sum + degree histogram
    k_edge<<<(E_EDGES + 255) / 256, 256>>>(w, src, dst);
    // K3: scan degrees -> rowstart, fold reciprocals
    k_scan<<<1, SCAN_THREADS>>>();
    // K4: scatter into CSR order with blended coefficients
    k_scatter<<<(E_EDGES + 255) / 256, 256>>>(src, dst);
    // K5: aggregate (warp per node, no atomics)
    {
        long long threadsTotal = (long long)N_NODES * 32;
        int grid = (int)((threadsTotal + 255) / 256);
        k_aggregate<<<grid, 256>>>(out, bias);
    }
}

// round 10
// speedup vs baseline: 1.7680x; 1.7680x over previous
#include <cuda_runtime.h>
#include <cuda_bf16.h>
#include <math_constants.h>

// Problem constants
#define N_NODES 50000
#define E_EDGES 800000
#define IN_F    256
#define OUT_F   128
#define NEG_SLOPE 0.2f
#define ALPHA   0.5f

#define SCAN_BLOCKS ((N_NODES + 255) / 256)   // 196

// -------- scratch (static device globals; no allocation allowed) --------
__device__ float g_ft[(size_t)N_NODES * OUT_F];   // projected features [N,128]
__device__ float g_el[N_NODES];
__device__ float g_er[N_NODES];
__device__ float g_sumE[N_NODES];   // sum -> reciprocal after scan phase a
__device__ float g_sumW[N_NODES];
__device__ float g_zE[E_EDGES];
__device__ float g_zW[E_EDGES];
__device__ int   g_deg[N_NODES];          // per-dst degree
__device__ int   g_rowstart[N_NODES + 1];
__device__ int   g_pos[N_NODES];          // working cursor for scatter
__device__ int   g_bsum[SCAN_BLOCKS];     // per-block degree totals -> prefixes
__device__ float g_a[E_EDGES];            // blended coefficient, CSR-permuted
__device__ int   g_srcp[E_EDGES];         // src node id, CSR-permuted

// -------- K0: zero softmax sums + degree counters --------
__global__ void k_init() {
    int i = blockIdx.x * blockDim.x + threadIdx.x;
    if (i < N_NODES) {
        g_sumE[i] = 0.0f;
        g_sumW[i] = 0.0f;
        g_deg[i]  = 0;
    }
}

// -------- K1: SGEMM ft = feat(50000x256) @ fc_w(256x128), fused el/er dots --------
#define BM 64
#define BN 128
#define BK 16
__global__ __launch_bounds__(256) void k_gemm(const float* __restrict__ A,
                                              const float* __restrict__ B,
                                              const float* __restrict__ attn_l,
                                              const float* __restrict__ attn_r) {
    __shared__ float As[BK][BM + 4];
    __shared__ float Bs[BK][BN];

    const int tid = threadIdx.x;
    const int tx = tid & 15;      // col group (8 cols each)
    const int ty = tid >> 4;      // row group (4 rows each)
    const int blockRow = blockIdx.x * BM;

    const int aRow  = tid >> 2;
    const int aCol4 = (tid & 3) << 2;
    const int bRow  = tid >> 5;
    const int bCol4 = (tid & 31) << 2;

    float acc[4][8];
#pragma unroll
    for (int r = 0; r < 4; r++)
#pragma unroll
        for (int c = 0; c < 8; c++) acc[r][c] = 0.0f;

    const int gRowA = blockRow + aRow;
    const bool aValid = (gRowA < N_NODES);
    const float* Aptr = A + (size_t)gRowA * IN_F + aCol4;

    for (int k0 = 0; k0 < IN_F; k0 += BK) {
        float4 av = aValid ? *(const float4*)(Aptr + k0)
                           : make_float4(0.f, 0.f, 0.f, 0.f);
        As[aCol4 + 0][aRow] = av.x;
        As[aCol4 + 1][aRow] = av.y;
        As[aCol4 + 2][aRow] = av.z;
        As[aCol4 + 3][aRow] = av.w;

        float4 bv0 = *(const float4*)&B[(size_t)(k0 + bRow) * OUT_F + bCol4];
        float4 bv1 = *(const float4*)&B[(size_t)(k0 + bRow + 8) * OUT_F + bCol4];
        *(float4*)&Bs[bRow][bCol4]     = bv0;
        *(float4*)&Bs[bRow + 8][bCol4] = bv1;

        __syncthreads();

#pragma unroll
        for (int k = 0; k < BK; k++) {
            float ar[4], br[8];
#pragma unroll
            for (int r = 0; r < 4; r++) ar[r] = As[k][ty * 4 + r];
#pragma unroll
            for (int c = 0; c < 8; c++) br[c] = Bs[k][tx * 8 + c];
#pragma unroll
            for (int r = 0; r < 4; r++)
#pragma unroll
                for (int c = 0; c < 8; c++) acc[r][c] = fmaf(ar[r], br[c], acc[r][c]);
        }
        __syncthreads();
    }

    float al[8], arr[8];
#pragma unroll
    for (int c = 0; c < 8; c++) {
        al[c]  = attn_l[tx * 8 + c];
        arr[c] = attn_r[tx * 8 + c];
    }

#pragma unroll
    for (int r = 0; r < 4; r++) {
        int gRow = blockRow + ty * 4 + r;
        bool valid = (gRow < N_NODES);
        if (valid) {
            float* o = &g_ft[(size_t)gRow * OUT_F + tx * 8];
            *(float4*)(o + 0) = make_float4(acc[r][0], acc[r][1], acc[r][2], acc[r][3]);
            *(float4*)(o + 4) = make_float4(acc[r][4], acc[r][5], acc[r][6], acc[r][7]);
        }
        float pl = 0.0f, pr = 0.0f;
#pragma unroll
        for (int c = 0; c < 8; c++) {
            pl = fmaf(acc[r][c], al[c],  pl);
            pr = fmaf(acc[r][c], arr[c], pr);
        }
#pragma unroll
        for (int off = 8; off > 0; off >>= 1) {
            pl += __shfl_down_sync(0xFFFFFFFFu, pl, off, 16);
            pr += __shfl_down_sync(0xFFFFFFFFu, pr, off, 16);
        }
        if (tx == 0 && valid) {
            g_el[gRow] = pl;
            g_er[gRow] = pr;
        }
    }
}

// -------- K2: edge pass: score + exp + segment sums + degree histogram --------
__global__ void k_edge(const float* __restrict__ w,
                       const int* __restrict__ src,
                       const int* __restrict__ dst) {
    int e = blockIdx.x * blockDim.x + threadIdx.x;
    if (e >= E_EDGES) return;
    int s = __ldg(&src[e]), d = __ldg(&dst[e]);
    float sc = g_el[s] + g_er[d];
    sc = (sc > 0.0f) ? sc : NEG_SLOPE * sc;
    float zE = __expf(sc);
    float zW = __expf(__ldg(&w[e]));
    g_zE[e] = zE;
    g_zW[e] = zW;
    atomicAdd(&g_sumE[d], zE);
    atomicAdd(&g_sumW[d], zW);
    atomicAdd(&g_deg[d], 1);
}

// -------- K3a: block-local exclusive scan of degrees + reciprocals --------
__global__ __launch_bounds__(256) void k_scan_a() {
    __shared__ int warp_tot[8];
    int tid  = threadIdx.x;
    int lane = tid & 31, wid = tid >> 5;
    int i = blockIdx.x * 256 + tid;

    int d = (i < N_NODES) ? g_deg[i] : 0;

    // warp inclusive scan
    int v = d;
#pragma unroll
    for (int off = 1; off < 32; off <<= 1) {
        int n = __shfl_up_sync(0xFFFFFFFFu, v, off);
        if (lane >= off) v += n;
    }
    if (lane == 31) warp_tot[wid] = v;
    __syncthreads();
    if (wid == 0 && lane < 8) {
        int s = warp_tot[lane];
#pragma unroll
        for (int off = 1; off < 8; off <<= 1) {
            int n = __shfl_up_sync(0xFFu, s, off);
            if (lane >= off) s += n;
        }
        warp_tot[lane] = s;
    }
    __syncthreads();
    int warp_prefix = (wid > 0) ? warp_tot[wid - 1] : 0;
    int excl = warp_prefix + (v - d);   // block-local exclusive prefix

    if (i < N_NODES) {
        g_rowstart[i] = excl;           // block offset added in phase c
        // fold reciprocal pass (elementwise)
        float sE = g_sumE[i], sW = g_sumW[i];
        g_sumE[i] = (sE > 0.0f) ? 1.0f / sE : 0.0f;
        g_sumW[i] = (sW > 0.0f) ? 1.0f / sW : 0.0f;
    }
    if (tid == 255) g_bsum[blockIdx.x] = excl + d;  // block total
}

// -------- K3b: exclusive scan of block sums (one block; SCAN_BLOCKS <= 256) --------
__global__ __launch_bounds__(256) void k_scan_b() {
    __shared__ int warp_tot[8];
    int tid  = threadIdx.x;
    int lane = tid & 31, wid = tid >> 5;

    int d = (tid < SCAN_BLOCKS) ? g_bsum[tid] : 0;
    int v = d;
#pragma unroll
    for (int off = 1; off < 32; off <<= 1) {
        int n = __shfl_up_sync(0xFFFFFFFFu, v, off);
        if (lane >= off) v += n;
    }
    if (lane == 31) warp_tot[wid] = v;
    __syncthreads();
    if (wid == 0 && lane < 8) {
        int s = warp_tot[lane];
#pragma unroll
        for (int off = 1; off < 8; off <<= 1) {
            int n = __shfl_up_sync(0xFFu, s, off);
            if (lane >= off) s += n;
        }
        warp_tot[lane] = s;
    }
    __syncthreads();
    int warp_prefix = (wid > 0) ? warp_tot[wid - 1] : 0;
    int excl = warp_prefix + (v - d);
    if (tid < SCAN_BLOCKS) g_bsum[tid] = excl;
}

// -------- K3c: add block offsets, init scatter cursors, cap rowstart --------
__global__ __launch_bounds__(256) void k_scan_c() {
    int i = blockIdx.x * 256 + threadIdx.x;
    if (i < N_NODES) {
        int rs = g_rowstart[i] + g_bsum[blockIdx.x];
        g_rowstart[i] = rs;
        g_pos[i] = rs;
    }
    if (i == 0) g_rowstart[N_NODES] = E_EDGES;  // every edge has a valid dst
}

// -------- K4: scatter edges into CSR order, with final blended coefficient --------
__global__ void k_scatter(const int* __restrict__ src,
                          const int* __restrict__ dst) {
    int e = blockIdx.x * blockDim.x + threadIdx.x;
    if (e >= E_EDGES) return;
    int d = __ldg(&dst[e]);
    float coef = (1.0f - ALPHA) * g_zE[e] * g_sumE[d]
               + ALPHA * g_zW[e] * g_sumW[d];
    int pos = atomicAdd(&g_pos[d], 1);
    g_a[pos]    = coef;
    g_srcp[pos] = __ldg(&src[e]);
}

// -------- K5: aggregation: warp per node, register accumulate, single store --------
__global__ __launch_bounds__(256) void k_aggregate(float* __restrict__ out,
                                                   const float* __restrict__ bias) {
    int node = (blockIdx.x * blockDim.x + threadIdx.x) >> 5;
    int lane = threadIdx.x & 31;
    if (node >= N_NODES) return;

    int start = g_rowstart[node];
    int end   = g_rowstart[node + 1];

    float4 acc = ((const float4*)bias)[lane];

    for (int t = start; t < end; t += 32) {
        int cnt = min(32, end - t);
        float a = 0.0f;
        int   s = 0;
        if (lane < cnt) {
            a = g_a[t + lane];
            s = g_srcp[t + lane];
        }
#pragma unroll 4
        for (int k = 0; k < cnt; k++) {
            float ak = __shfl_sync(0xFFFFFFFFu, a, k);
            int   sk = __shfl_sync(0xFFFFFFFFu, s, k);
            float4 v = ((const float4*)&g_ft[(size_t)sk * OUT_F])[lane];
            acc.x = fmaf(v.x, ak, acc.x);
            acc.y = fmaf(v.y, ak, acc.y);
            acc.z = fmaf(v.z, ak, acc.z);
            acc.w = fmaf(v.w, ak, acc.w);
        }
    }

    ((float4*)&out[(size_t)node * OUT_F])[lane] = acc;
}

// -------- launch --------
extern "C" void kernel_launch(void* const* d_in, const int* in_sizes, int n_in,
                              void* d_out, int out_size) {
    const float* feat   = (const float*)d_in[0];  // [N,256]
    const float* w      = (const float*)d_in[1];  // [E]
    const float* fc_w   = (const float*)d_in[2];  // [256,128]
    const float* attn_l = (const float*)d_in[3];  // [128]
    const float* attn_r = (const float*)d_in[4];  // [128]
    const float* bias   = (const float*)d_in[5];  // [128]
    const int*   src    = (const int*)d_in[6];    // [E]
    const int*   dst    = (const int*)d_in[7];    // [E]
    float* out = (float*)d_out;                   // [N,1,128]

    // K0: zero sums + degrees
    k_init<<<(N_NODES + 255) / 256, 256>>>();
    // K1: GEMM + fused el/er
    {
        int grid = (N_NODES + BM - 1) / BM;
        k_gemm<<<grid, 256>>>(feat, fc_w, attn_l, attn_r);
    }
    // K2: edge score/exp/sum + degree histogram
    k_edge<<<(E_EDGES + 255) / 256, 256>>>(w, src, dst);
    // K3: parallel scan (3 phases) + reciprocals
    k_scan_a<<<SCAN_BLOCKS, 256>>>();
    k_scan_b<<<1, 256>>>();
    k_scan_c<<<SCAN_BLOCKS, 256>>>();
    // K4: scatter into CSR order with blended coefficients
    k_scatter<<<(E_EDGES + 255) / 256, 256>>>(src, dst);
    // K5: aggregate (warp per node, no atomics)
    {
        long long threadsTotal = (long long)N_NODES * 32;
        int grid = (int)((threadsTotal + 255) / 256);
        k_aggregate<<<grid, 256>>>(out, bias);
    }
}

// round 11
// speedup vs baseline: 1.8530x; 1.0481x over previous
#include <cuda_runtime.h>
#include <cuda_bf16.h>
#include <math_constants.h>

// Problem constants
#define N_NODES 50000
#define E_EDGES 800000
#define IN_F    256
#define OUT_F   128
#define NEG_SLOPE 0.2f
#define ALPHA   0.5f

#define SCAN_BLOCKS ((N_NODES + 255) / 256)   // 196

// -------- scratch (static device globals; no allocation allowed) --------
__device__ float g_ft[(size_t)N_NODES * OUT_F];   // projected features [N,128]
__device__ float g_el[N_NODES];
__device__ float g_er[N_NODES];
__device__ float g_sumE[N_NODES];
__device__ float g_sumW[N_NODES];
__device__ int   g_deg[N_NODES];          // per-dst degree
__device__ int   g_rowstart[N_NODES + 1];
__device__ int   g_pos[N_NODES];          // working cursor for scatter
__device__ int   g_bsum[SCAN_BLOCKS];     // per-block degree totals -> prefixes
__device__ float g_zEp[E_EDGES];          // exp(score), CSR-permuted
__device__ float g_zWp[E_EDGES];          // exp(w), CSR-permuted
__device__ int   g_srcp[E_EDGES];         // src node id, CSR-permuted

// -------- side stream + events for GEMM || CSR-build overlap --------
// Created once at program load (host-side resources only; no device memory).
static cudaStream_t g_s2;
static cudaEvent_t  g_evFork, g_evGemm;
namespace {
struct StreamInit {
    StreamInit() {
        cudaStreamCreateWithFlags(&g_s2, cudaStreamNonBlocking);
        cudaEventCreateWithFlags(&g_evFork, cudaEventDisableTiming);
        cudaEventCreateWithFlags(&g_evGemm, cudaEventDisableTiming);
    }
};
static StreamInit g_streamInit;
}

// -------- K0: zero softmax sums + degree counters --------
__global__ void k_init() {
    int i = blockIdx.x * blockDim.x + threadIdx.x;
    if (i < N_NODES) {
        g_sumE[i] = 0.0f;
        g_sumW[i] = 0.0f;
        g_deg[i]  = 0;
    }
}

// -------- K1 (side stream): SGEMM ft = feat @ fc_w, fused el/er dots --------
#define BM 64
#define BN 128
#define BK 16
__global__ __launch_bounds__(256) void k_gemm(const float* __restrict__ A,
                                              const float* __restrict__ B,
                                              const float* __restrict__ attn_l,
                                              const float* __restrict__ attn_r) {
    __shared__ float As[BK][BM + 4];
    __shared__ float Bs[BK][BN];

    const int tid = threadIdx.x;
    const int tx = tid & 15;      // col group (8 cols each)
    const int ty = tid >> 4;      // row group (4 rows each)
    const int blockRow = blockIdx.x * BM;

    const int aRow  = tid >> 2;
    const int aCol4 = (tid & 3) << 2;
    const int bRow  = tid >> 5;
    const int bCol4 = (tid & 31) << 2;

    float acc[4][8];
#pragma unroll
    for (int r = 0; r < 4; r++)
#pragma unroll
        for (int c = 0; c < 8; c++) acc[r][c] = 0.0f;

    const int gRowA = blockRow + aRow;
    const bool aValid = (gRowA < N_NODES);
    const float* Aptr = A + (size_t)gRowA * IN_F + aCol4;

    for (int k0 = 0; k0 < IN_F; k0 += BK) {
        float4 av = aValid ? *(const float4*)(Aptr + k0)
                           : make_float4(0.f, 0.f, 0.f, 0.f);
        As[aCol4 + 0][aRow] = av.x;
        As[aCol4 + 1][aRow] = av.y;
        As[aCol4 + 2][aRow] = av.z;
        As[aCol4 + 3][aRow] = av.w;

        float4 bv0 = *(const float4*)&B[(size_t)(k0 + bRow) * OUT_F + bCol4];
        float4 bv1 = *(const float4*)&B[(size_t)(k0 + bRow + 8) * OUT_F + bCol4];
        *(float4*)&Bs[bRow][bCol4]     = bv0;
        *(float4*)&Bs[bRow + 8][bCol4] = bv1;

        __syncthreads();

#pragma unroll
        for (int k = 0; k < BK; k++) {
            float ar[4], br[8];
#pragma unroll
            for (int r = 0; r < 4; r++) ar[r] = As[k][ty * 4 + r];
#pragma unroll
            for (int c = 0; c < 8; c++) br[c] = Bs[k][tx * 8 + c];
#pragma unroll
            for (int r = 0; r < 4; r++)
#pragma unroll
                for (int c = 0; c < 8; c++) acc[r][c] = fmaf(ar[r], br[c], acc[r][c]);
        }
        __syncthreads();
    }

    float al[8], arr[8];
#pragma unroll
    for (int c = 0; c < 8; c++) {
        al[c]  = attn_l[tx * 8 + c];
        arr[c] = attn_r[tx * 8 + c];
    }

#pragma unroll
    for (int r = 0; r < 4; r++) {
        int gRow = blockRow + ty * 4 + r;
        bool valid = (gRow < N_NODES);
        if (valid) {
            float* o = &g_ft[(size_t)gRow * OUT_F + tx * 8];
            *(float4*)(o + 0) = make_float4(acc[r][0], acc[r][1], acc[r][2], acc[r][3]);
            *(float4*)(o + 4) = make_float4(acc[r][4], acc[r][5], acc[r][6], acc[r][7]);
        }
        float pl = 0.0f, pr = 0.0f;
#pragma unroll
        for (int c = 0; c < 8; c++) {
            pl = fmaf(acc[r][c], al[c],  pl);
            pr = fmaf(acc[r][c], arr[c], pr);
        }
#pragma unroll
        for (int off = 8; off > 0; off >>= 1) {
            pl += __shfl_down_sync(0xFFFFFFFFu, pl, off, 16);
            pr += __shfl_down_sync(0xFFFFFFFFu, pr, off, 16);
        }
        if (tx == 0 && valid) {
            g_el[gRow] = pl;
            g_er[gRow] = pr;
        }
    }
}

// -------- K2 (main stream): degree histogram (dst only; GEMM-independent) ----
__global__ void k_deg(const int* __restrict__ dst) {
    int e = blockIdx.x * blockDim.x + threadIdx.x;
    if (e >= E_EDGES) return;
    atomicAdd(&g_deg[__ldg(&dst[e])], 1);
}

// -------- K3a: block-local exclusive scan of degrees --------
__global__ __launch_bounds__(256) void k_scan_a() {
    __shared__ int warp_tot[8];
    int tid  = threadIdx.x;
    int lane = tid & 31, wid = tid >> 5;
    int i = blockIdx.x * 256 + tid;

    int d = (i < N_NODES) ? g_deg[i] : 0;

    int v = d;
#pragma unroll
    for (int off = 1; off < 32; off <<= 1) {
        int n = __shfl_up_sync(0xFFFFFFFFu, v, off);
        if (lane >= off) v += n;
    }
    if (lane == 31) warp_tot[wid] = v;
    __syncthreads();
    if (wid == 0 && lane < 8) {
        int s = warp_tot[lane];
#pragma unroll
        for (int off = 1; off < 8; off <<= 1) {
            int n = __shfl_up_sync(0xFFu, s, off);
            if (lane >= off) s += n;
        }
        warp_tot[lane] = s;
    }
    __syncthreads();
    int warp_prefix = (wid > 0) ? warp_tot[wid - 1] : 0;
    int excl = warp_prefix + (v - d);

    if (i < N_NODES) g_rowstart[i] = excl;
    if (tid == 255) g_bsum[blockIdx.x] = excl + d;
}

// -------- K3b: exclusive scan of block sums (one block; SCAN_BLOCKS <= 256) --
__global__ __launch_bounds__(256) void k_scan_b() {
    __shared__ int warp_tot[8];
    int tid  = threadIdx.x;
    int lane = tid & 31, wid = tid >> 5;

    int d = (tid < SCAN_BLOCKS) ? g_bsum[tid] : 0;
    int v = d;
#pragma unroll
    for (int off = 1; off < 32; off <<= 1) {
        int n = __shfl_up_sync(0xFFFFFFFFu, v, off);
        if (lane >= off) v += n;
    }
    if (lane == 31) warp_tot[wid] = v;
    __syncthreads();
    if (wid == 0 && lane < 8) {
        int s = warp_tot[lane];
#pragma unroll
        for (int off = 1; off < 8; off <<= 1) {
            int n = __shfl_up_sync(0xFFu, s, off);
            if (lane >= off) s += n;
        }
        warp_tot[lane] = s;
    }
    __syncthreads();
    int warp_prefix = (wid > 0) ? warp_tot[wid - 1] : 0;
    int excl = warp_prefix + (v - d);
    if (tid < SCAN_BLOCKS) g_bsum[tid] = excl;
}

// -------- K3c: add block offsets, init scatter cursors, cap rowstart --------
__global__ __launch_bounds__(256) void k_scan_c() {
    int i = blockIdx.x * 256 + threadIdx.x;
    if (i < N_NODES) {
        int rs = g_rowstart[i] + g_bsum[blockIdx.x];
        g_rowstart[i] = rs;
        g_pos[i] = rs;
    }
    if (i == 0) g_rowstart[N_NODES] = E_EDGES;
}

// -------- K4: fused edge pass: score + exp + sums + CSR scatter --------
// (joins both streams: needs el/er from GEMM and pos/rowstart from scan)
__global__ void k_edge(const float* __restrict__ w,
                       const int* __restrict__ src,
                       const int* __restrict__ dst) {
    int e = blockIdx.x * blockDim.x + threadIdx.x;
    if (e >= E_EDGES) return;
    int s = __ldg(&src[e]), d = __ldg(&dst[e]);
    float sc = g_el[s] + g_er[d];
    sc = (sc > 0.0f) ? sc : NEG_SLOPE * sc;
    float zE = __expf(sc);
    float zW = __expf(__ldg(&w[e]));
    atomicAdd(&g_sumE[d], zE);
    atomicAdd(&g_sumW[d], zW);
    int pos = atomicAdd(&g_pos[d], 1);
    g_zEp[pos]  = zE;
    g_zWp[pos]  = zW;
    g_srcp[pos] = s;
}

// -------- K5: aggregation: warp per node, inline coef, no atomics --------
__global__ __launch_bounds__(256) void k_aggregate(float* __restrict__ out,
                                                   const float* __restrict__ bias) {
    int node = (blockIdx.x * blockDim.x + threadIdx.x) >> 5;
    int lane = threadIdx.x & 31;
    if (node >= N_NODES) return;

    int start = g_rowstart[node];
    int end   = g_rowstart[node + 1];

    float4 acc = ((const float4*)bias)[lane];

    if (start < end) {
        // per-node reciprocals (warp-uniform; sums > 0 since node has edges)
        float rE = (1.0f - ALPHA) / g_sumE[node];
        float rW = ALPHA / g_sumW[node];

        for (int t = start; t < end; t += 32) {
            int cnt = min(32, end - t);
            float a = 0.0f;
            int   s = 0;
            if (lane < cnt) {
                a = fmaf(g_zEp[t + lane], rE, g_zWp[t + lane] * rW);
                s = g_srcp[t + lane];
            }
#pragma unroll 4
            for (int k = 0; k < cnt; k++) {
                float ak = __shfl_sync(0xFFFFFFFFu, a, k);
                int   sk = __shfl_sync(0xFFFFFFFFu, s, k);
                float4 v = ((const float4*)&g_ft[(size_t)sk * OUT_F])[lane];
                acc.x = fmaf(v.x, ak, acc.x);
                acc.y = fmaf(v.y, ak, acc.y);
                acc.z = fmaf(v.z, ak, acc.z);
                acc.w = fmaf(v.w, ak, acc.w);
            }
        }
    }

    ((float4*)&out[(size_t)node * OUT_F])[lane] = acc;
}

// -------- launch --------
extern "C" void kernel_launch(void* const* d_in, const int* in_sizes, int n_in,
                              void* d_out, int out_size) {
    const float* feat   = (const float*)d_in[0];  // [N,256]
    const float* w      = (const float*)d_in[1];  // [E]
    const float* fc_w   = (const float*)d_in[2];  // [256,128]
    const float* attn_l = (const float*)d_in[3];  // [128]
    const float* attn_r = (const float*)d_in[4];  // [128]
    const float* bias   = (const float*)d_in[5];  // [128]
    const int*   src    = (const int*)d_in[6];    // [E]
    const int*   dst    = (const int*)d_in[7];    // [E]
    float* out = (float*)d_out;                   // [N,1,128]

    // Fork: GEMM on side stream, CSR build on main stream (independent work).
    cudaEventRecord(g_evFork, 0);
    cudaStreamWaitEvent(g_s2, g_evFork, 0);
    {
        int grid = (N_NODES + BM - 1) / BM;
        k_gemm<<<grid, 256, 0, g_s2>>>(feat, fc_w, attn_l, attn_r);
    }
    cudaEventRecord(g_evGemm, g_s2);

    // Main stream: init + degree histogram + scan (dst-only, GEMM-independent)
    k_init<<<(N_NODES + 255) / 256, 256>>>();
    k_deg<<<(E_EDGES + 255) / 256, 256>>>(dst);
    k_scan_a<<<SCAN_BLOCKS, 256>>>();
    k_scan_b<<<1, 256>>>();
    k_scan_c<<<SCAN_BLOCKS, 256>>>();

    // Join: edge pass needs both el/er (GEMM) and pos (scan)
    cudaStreamWaitEvent(0, g_evGemm, 0);
    k_edge<<<(E_EDGES + 255) / 256, 256>>>(w, src, dst);

    // Aggregate (warp per node, no atomics, coef inline)
    {
        long long threadsTotal = (long long)N_NODES * 32;
        int grid = (int)((threadsTotal + 255) / 256);
        k_aggregate<<<grid, 256>>>(out, bias);
    }
}